// round 11
// baseline (speedup 1.0000x reference)
#include <cuda_runtime.h>
#include <cuda_fp16.h>
#include <mma.h>
#include <math.h>
#include <stdint.h>

using namespace nvcuda;

#define Bc 8
#define Sc 2048
#define Dc 1024
#define Ec 8
#define SUBD 128
#define SUBH 512
#define SD (Sc*Dc)
#define NCHUNKR 256
#define CHUNKR (SD/NCHUNKR)

// ---------------- scratch (static device globals) ----------------
__device__ float g_h1[16*Sc*SUBH];
__device__ float g_gsel[(long)Bc*Sc*2*SUBH];
__device__ float g_part[NCHUNKR*Bc*Ec];
__device__ int   g_sel[Bc*2];

__device__ __forceinline__ float gelu_exact(float v) {
    return 0.5f * v * (1.0f + erff(v * 0.70710678118654752440f));
}

// ============================================================
// Routing (R1 verbatim — proven)
// ============================================================
__global__ void route_partial_kernel(const float* __restrict__ x,
                                     const float* __restrict__ w) {
    const int chunk = blockIdx.x;
    const int tid   = threadIdx.x;

    float acc[Bc][Ec];
#pragma unroll
    for (int b = 0; b < Bc; b++)
#pragma unroll
        for (int e = 0; e < Ec; e++) acc[b][e] = 0.f;

    const long base = (long)chunk * CHUNKR;
    for (int it = 0; it < CHUNKR / 256; it++) {
        const long i = base + it * 256 + tid;
        const float4 w0 = *(const float4*)(w + i * 8);
        const float4 w1v = *(const float4*)(w + i * 8 + 4);
        const float wv[8] = {w0.x, w0.y, w0.z, w0.w, w1v.x, w1v.y, w1v.z, w1v.w};
#pragma unroll
        for (int b = 0; b < Bc; b++) {
            const float xv = x[(long)b * SD + i];
#pragma unroll
            for (int e = 0; e < Ec; e++) acc[b][e] = fmaf(xv, wv[e], acc[b][e]);
        }
    }

    __shared__ float sm[8][64];
    const int lane = tid & 31, warp = tid >> 5;
#pragma unroll
    for (int b = 0; b < Bc; b++) {
#pragma unroll
        for (int e = 0; e < Ec; e++) {
            float v = acc[b][e];
#pragma unroll
            for (int o = 16; o > 0; o >>= 1) v += __shfl_down_sync(0xffffffffu, v, o);
            if (lane == 0) sm[warp][b * 8 + e] = v;
        }
    }
    __syncthreads();
    if (tid < 64) {
        float s = 0.f;
#pragma unroll
        for (int w2 = 0; w2 < 8; w2++) s += sm[w2][tid];
        g_part[chunk * 64 + tid] = s;
    }
}

__global__ void route_topk_kernel(const float* __restrict__ b_switch) {
    __shared__ float lg[64];
    const int t = threadIdx.x;
    float s = b_switch[t & 7];
    for (int c = 0; c < NCHUNKR; c++) s += g_part[c * 64 + t];
    lg[t] = s;
    __syncthreads();
    if (t < Bc) {
        const float* L = lg + t * 8;
        int i0 = 0; float v0 = L[0];
#pragma unroll
        for (int e = 1; e < 8; e++) if (L[e] > v0) { v0 = L[e]; i0 = e; }
        int i1 = -1; float v1 = -3.0e38f;
#pragma unroll
        for (int e = 0; e < 8; e++) if (e != i0 && L[e] > v1) { v1 = L[e]; i1 = e; }
        g_sel[t * 2 + 0] = i0;
        g_sel[t * 2 + 1] = i1;
    }
}

// ============================================================
// WMMA fp16 2-term split GEMM (A = Ah+Al fp16, B = single fp16),
// in-kernel conversion, double-buffered BK=16, register prefetch.
// CTA tile 128x256, 8 warps (4x2), warp tile 32x128 = 2x8 frags.
//   A block: 128 rows x [hi16|lo16|pad8] = 40 halfs/row (80B)
//   B block: 16 k-rows x [256 halfs|pad8] = 264 halfs/row (528B)
//   stage = 128*40 + 16*264 = 9344 halfs; 2 stages = 37376B < 48KB
// MODE 0: g_h1  = gelu(x[:, e*128:+128] @ w1[e] + b1[e])   K=128
// MODE 1: g_gsel= gelu(g_h1 @ w2[e] + b2[e])               K=512
// MODE 2: out   = g_gsel @ gather(w_out) + b_out           K=1024
// ============================================================
#define AROWE 40
#define ABLK  (128*AROWE)     // 5120 halfs
#define BROWE 264
#define BBLK  (16*BROWE)      // 4224 halfs
#define STAGE_E (ABLK + BBLK) // 9344 halfs
#define SMEM_ALLOC (2*STAGE_E*2)  // 37376 bytes

__device__ __forceinline__ uint32_t pack_h2(float a, float b) {
    __half2 h; h.x = __float2half_rn(a); h.y = __float2half_rn(b);
    return *(uint32_t*)&h;
}

template <int MODE>
__global__ void __launch_bounds__(256)
conv_wmma_gemm(const float* __restrict__ A0, const float* __restrict__ B0,
               const float* __restrict__ bias0, float* __restrict__ outp) {
    extern __shared__ __half smem[];

    const int tid = threadIdx.x;
    const int z = blockIdx.z;
    const int rowBlock = blockIdx.y * 128;
    const int colBlock = blockIdx.x * 256;
    const int warp = tid >> 5, lane = tid & 31;
    const int wm = warp & 3, wn = warp >> 2;   // warp tile: rows wm*32..+32, cols wn*128..+128

    const float* A;
    const float* Bp;
    const float* bias;
    int lda, ldn, akbase, nstages, e0 = 0, e1 = 0;
    if (MODE == 0) {
        const int e = g_sel[z];
        A = A0 + (size_t)(z >> 1) * SD; lda = Dc; akbase = e * SUBD;
        Bp = B0 + (size_t)e * SUBD * SUBH; ldn = SUBH;
        bias = bias0 + e * SUBH;
        nstages = SUBD / 16;
    } else if (MODE == 1) {
        const int e = g_sel[z];
        A = g_h1 + (size_t)z * Sc * SUBH; lda = SUBH; akbase = 0;
        Bp = B0 + (size_t)e * SUBH * SUBH; ldn = SUBH;
        bias = bias0 + e * SUBH;
        nstages = SUBH / 16;
    } else {
        A = g_gsel + (size_t)z * Sc * (2 * SUBH); lda = 2 * SUBH; akbase = 0;
        Bp = B0; ldn = Dc;
        bias = bias0;
        nstages = (2 * SUBH) / 16;
        e0 = g_sel[z * 2]; e1 = g_sel[z * 2 + 1];
    }

    wmma::fragment<wmma::accumulator, 16, 16, 16, float> acc[2][8];
#pragma unroll
    for (int mt = 0; mt < 2; mt++)
#pragma unroll
        for (int nt = 0; nt < 8; nt++) wmma::fill_fragment(acc[mt][nt], 0.0f);

    float4 pa[2], pb[4];

    auto loadRegs = [&](int c) {
        const int ak0 = akbase + c * 16;
        const int bk0 = c * 16;
#pragma unroll
        for (int j = 0; j < 2; j++) {     // A: 512 float4
            const int idx = tid + j * 256;
            const int m = idx >> 2, ks = idx & 3;
            pa[j] = *(const float4*)(A + (size_t)(rowBlock + m) * lda + ak0 + ks * 4);
        }
#pragma unroll
        for (int j = 0; j < 4; j++) {     // B: 1024 float4 (16 k x 256 n)
            const int idx = tid + j * 256;
            const int k = idx >> 6, ns = idx & 63;
            const int kg = bk0 + k;
            const float* brow;
            if (MODE == 2) {
                const int r = (kg < SUBH) ? (e0 * SUBH + kg) : (e1 * SUBH + kg - SUBH);
                brow = Bp + (size_t)r * Dc;
            } else {
                brow = Bp + (size_t)kg * ldn;
            }
            pb[j] = *(const float4*)(brow + colBlock + ns * 4);
        }
    };

    auto convStore = [&](int st) {
        __half* s = smem + st * STAGE_E;
#pragma unroll
        for (int j = 0; j < 2; j++) {     // A: fp16 hi + residual lo
            const int idx = tid + j * 256;
            const int m = idx >> 2, ks = idx & 3;
            const float4 v = pa[j];
            const float hx = __half2float(__float2half_rn(v.x));
            const float hy = __half2float(__float2half_rn(v.y));
            const float hz = __half2float(__float2half_rn(v.z));
            const float hw = __half2float(__float2half_rn(v.w));
            uint2 hi, lo;
            hi.x = pack_h2(v.x, v.y);           hi.y = pack_h2(v.z, v.w);
            lo.x = pack_h2(v.x - hx, v.y - hy); lo.y = pack_h2(v.z - hz, v.w - hw);
            *(uint2*)(s + m * AROWE + ks * 4)      = hi;
            *(uint2*)(s + m * AROWE + 16 + ks * 4) = lo;
        }
#pragma unroll
        for (int j = 0; j < 4; j++) {     // B: single fp16
            const int idx = tid + j * 256;
            const int k = idx >> 6, ns = idx & 63;
            const float4 v = pb[j];
            uint2 hv;
            hv.x = pack_h2(v.x, v.y); hv.y = pack_h2(v.z, v.w);
            *(uint2*)(s + ABLK + k * BROWE + ns * 4) = hv;
        }
    };

    // prologue: fill stage 0
    loadRegs(0);
    convStore(0);
    __syncthreads();

    for (int c = 0; c < nstages; c++) {
        if (c + 1 < nstages) loadRegs(c + 1);   // issue next global loads early

        // ---- compute chunk c from stage c&1 ----
        const __half* s = smem + (c & 1) * STAGE_E;
        wmma::fragment<wmma::matrix_a, 16, 16, 16, __half, wmma::row_major> ah[2], al[2];
#pragma unroll
        for (int mt = 0; mt < 2; mt++) {
            const __half* ab = s + (wm * 32 + mt * 16) * AROWE;
            wmma::load_matrix_sync(ah[mt], ab, AROWE);
            wmma::load_matrix_sync(al[mt], ab + 16, AROWE);
        }
#pragma unroll
        for (int nt = 0; nt < 8; nt++) {
            wmma::fragment<wmma::matrix_b, 16, 16, 16, __half, wmma::row_major> bf;
            wmma::load_matrix_sync(bf, s + ABLK + (wn * 128 + nt * 16), BROWE);
#pragma unroll
            for (int mt = 0; mt < 2; mt++) {
                wmma::mma_sync(acc[mt][nt], ah[mt], bf, acc[mt][nt]);
                wmma::mma_sync(acc[mt][nt], al[mt], bf, acc[mt][nt]);
            }
        }

        if (c + 1 < nstages) convStore((c + 1) & 1);
        __syncthreads();
    }

    // ---- epilogue (R10-proven core, 8 n-frags in 2 groups of 4) ----
    float* scr = (float*)smem + warp * (16 * 68);
    const int srow = lane >> 1;
    const int cb = (lane & 1) * 32;

#pragma unroll
    for (int mt = 0; mt < 2; mt++) {
#pragma unroll
        for (int half = 0; half < 2; half++) {
#pragma unroll
            for (int i = 0; i < 4; i++)
                wmma::store_matrix_sync(scr + i * 16, acc[mt][half * 4 + i], 68,
                                        wmma::mem_row_major);
            __syncwarp();

            const int grow = rowBlock + wm * 32 + mt * 16 + srow;
            const int gcol0 = colBlock + wn * 128 + half * 64 + cb;

            if (MODE == 2) {
                float* orow = outp + (size_t)(z * Sc + grow) * Dc + gcol0;
#pragma unroll
                for (int cc = 0; cc < 32; cc += 2) {
                    const float v0 = scr[srow * 68 + cb + cc]     + bias[gcol0 + cc];
                    const float v1 = scr[srow * 68 + cb + cc + 1] + bias[gcol0 + cc + 1];
                    *(float2*)(orow + cc) = make_float2(v0, v1);
                }
            } else {
                float* dst;
                if (MODE == 0) {
                    dst = g_h1 + (size_t)(z * Sc + grow) * SUBH + gcol0;
                } else {
                    dst = g_gsel + (size_t)((z >> 1) * Sc + grow) * (2 * SUBH)
                        + (z & 1) * SUBH + gcol0;
                }
#pragma unroll
                for (int cc = 0; cc < 32; cc += 2) {
                    const float g0 = gelu_exact(scr[srow * 68 + cb + cc]     + bias[gcol0 + cc]);
                    const float g1 = gelu_exact(scr[srow * 68 + cb + cc + 1] + bias[gcol0 + cc + 1]);
                    *(float2*)(dst + cc) = make_float2(g0, g1);
                }
            }
            __syncwarp();
        }
    }
}

// ============================================================
extern "C" void kernel_launch(void* const* d_in, const int* in_sizes, int n_in,
                              void* d_out, int out_size) {
    const float* x        = (const float*)d_in[0];
    const float* w_switch = (const float*)d_in[1];
    const float* b_switch = (const float*)d_in[2];
    const float* w1       = (const float*)d_in[3];
    const float* b1       = (const float*)d_in[4];
    const float* w2       = (const float*)d_in[5];
    const float* b2       = (const float*)d_in[6];
    const float* w_out    = (const float*)d_in[7];
    const float* b_out    = (const float*)d_in[8];
    float* out = (float*)d_out;

    // 1) routing (proven)
    route_partial_kernel<<<NCHUNKR, 256>>>(x, w_switch);
    route_topk_kernel<<<1, 64>>>(b_switch);

    // 2) fp16 2-term WMMA expert MLP, 128x256 tiles, double-buffered
    conv_wmma_gemm<0><<<dim3(SUBH / 256, Sc / 128, 16), 256, SMEM_ALLOC>>>(x, w1, b1, nullptr);
    conv_wmma_gemm<1><<<dim3(SUBH / 256, Sc / 128, 16), 256, SMEM_ALLOC>>>(nullptr, w2, b2, nullptr);
    conv_wmma_gemm<2><<<dim3(Dc / 256, Sc / 128, Bc), 256, SMEM_ALLOC>>>(nullptr, w_out, b_out, out);
}

// round 12
// speedup vs baseline: 1.0812x; 1.0812x over previous
#include <cuda_runtime.h>
#include <cuda_fp16.h>
#include <mma.h>
#include <math.h>
#include <stdint.h>

using namespace nvcuda;

#define Bc 8
#define Sc 2048
#define Dc 1024
#define Ec 8
#define SUBD 128
#define SUBH 512
#define SD (Sc*Dc)
#define NCHUNKR 256
#define CHUNKR (SD/NCHUNKR)

// ---------------- scratch (static device globals) ----------------
__device__ float g_h1[16*Sc*SUBH];
__device__ float g_gsel[(long)Bc*Sc*2*SUBH];
__device__ float g_part[NCHUNKR*Bc*Ec];
__device__ int   g_sel[Bc*2];

__device__ __forceinline__ float gelu_exact(float v) {
    return 0.5f * v * (1.0f + erff(v * 0.70710678118654752440f));
}

// ============================================================
// Routing (R1 verbatim — proven)
// ============================================================
__global__ void route_partial_kernel(const float* __restrict__ x,
                                     const float* __restrict__ w) {
    const int chunk = blockIdx.x;
    const int tid   = threadIdx.x;

    float acc[Bc][Ec];
#pragma unroll
    for (int b = 0; b < Bc; b++)
#pragma unroll
        for (int e = 0; e < Ec; e++) acc[b][e] = 0.f;

    const long base = (long)chunk * CHUNKR;
    for (int it = 0; it < CHUNKR / 256; it++) {
        const long i = base + it * 256 + tid;
        const float4 w0 = *(const float4*)(w + i * 8);
        const float4 w1v = *(const float4*)(w + i * 8 + 4);
        const float wv[8] = {w0.x, w0.y, w0.z, w0.w, w1v.x, w1v.y, w1v.z, w1v.w};
#pragma unroll
        for (int b = 0; b < Bc; b++) {
            const float xv = x[(long)b * SD + i];
#pragma unroll
            for (int e = 0; e < Ec; e++) acc[b][e] = fmaf(xv, wv[e], acc[b][e]);
        }
    }

    __shared__ float sm[8][64];
    const int lane = tid & 31, warp = tid >> 5;
#pragma unroll
    for (int b = 0; b < Bc; b++) {
#pragma unroll
        for (int e = 0; e < Ec; e++) {
            float v = acc[b][e];
#pragma unroll
            for (int o = 16; o > 0; o >>= 1) v += __shfl_down_sync(0xffffffffu, v, o);
            if (lane == 0) sm[warp][b * 8 + e] = v;
        }
    }
    __syncthreads();
    if (tid < 64) {
        float s = 0.f;
#pragma unroll
        for (int w2 = 0; w2 < 8; w2++) s += sm[w2][tid];
        g_part[chunk * 64 + tid] = s;
    }
}

__global__ void route_topk_kernel(const float* __restrict__ b_switch) {
    __shared__ float lg[64];
    const int t = threadIdx.x;
    float s = b_switch[t & 7];
    for (int c = 0; c < NCHUNKR; c++) s += g_part[c * 64 + t];
    lg[t] = s;
    __syncthreads();
    if (t < Bc) {
        const float* L = lg + t * 8;
        int i0 = 0; float v0 = L[0];
#pragma unroll
        for (int e = 1; e < 8; e++) if (L[e] > v0) { v0 = L[e]; i0 = e; }
        int i1 = -1; float v1 = -3.0e38f;
#pragma unroll
        for (int e = 0; e < 8; e++) if (e != i0 && L[e] > v1) { v1 = L[e]; i1 = e; }
        g_sel[t * 2 + 0] = i0;
        g_sel[t * 2 + 1] = i1;
    }
}

// ============================================================
// WMMA fp16 2-term split GEMM (A = Ah+Al fp16, B = single fp16).
// R10 shape (CTA 128x128, 8 warps 32x64, BK=16, double-buffered,
// 2 CTAs/SM) with hoisted pointer arithmetic + packed conversions.
//   A block: 128 rows x [hi16|lo16|pad8] = 40 halfs/row
//   B block: 16 k-rows x [128 halfs|pad8] = 136 halfs/row
//   stage = 7296 halfs (14592B); alloc = 34816B (epilogue scratch)
// ============================================================
#define AROWE 40
#define ABLK  (128*AROWE)
#define BROWE 136
#define BBLK  (16*BROWE)
#define STAGE_E (ABLK + BBLK)
#define SMEM_ALLOC 34816

template <int MODE>
__global__ void __launch_bounds__(256)
conv_wmma_gemm(const float* __restrict__ A0, const float* __restrict__ B0,
               const float* __restrict__ bias0, float* __restrict__ outp) {
    extern __shared__ __half smem[];

    const int tid = threadIdx.x;
    const int z = blockIdx.z;
    const int rowBlock = blockIdx.y * 128;
    const int colBlock = blockIdx.x * 128;
    const int warp = tid >> 5, lane = tid & 31;
    const int wm = warp & 3, wn = warp >> 2;

    const float* A;
    const float* Bp;
    const float* bias;
    int lda, ldn, akbase, nstages, e0 = 0, e1 = 0;
    if (MODE == 0) {
        const int e = g_sel[z];
        A = A0 + (size_t)(z >> 1) * SD; lda = Dc; akbase = e * SUBD;
        Bp = B0 + (size_t)e * SUBD * SUBH; ldn = SUBH;
        bias = bias0 + e * SUBH;
        nstages = SUBD / 16;
    } else if (MODE == 1) {
        const int e = g_sel[z];
        A = g_h1 + (size_t)z * Sc * SUBH; lda = SUBH; akbase = 0;
        Bp = B0 + (size_t)e * SUBH * SUBH; ldn = SUBH;
        bias = bias0 + e * SUBH;
        nstages = SUBH / 16;
    } else {
        A = g_gsel + (size_t)z * Sc * (2 * SUBH); lda = 2 * SUBH; akbase = 0;
        Bp = B0; ldn = Dc;
        bias = bias0;
        nstages = (2 * SUBH) / 16;
        e0 = g_sel[z * 2]; e1 = g_sel[z * 2 + 1];
    }

    // ---- hoisted per-thread pointers ----
    // A loads: idx = tid + j*256; m = idx>>2, ks = idx&3
    const int mA0 = tid >> 2,           ksA0 = (tid & 3);
    const int mA1 = (tid + 256) >> 2,   ksA1 = (tid & 3);       // same ks pattern
    const float* pA0 = A + (size_t)(rowBlock + mA0) * lda + akbase + ksA0 * 4;
    const float* pA1 = A + (size_t)(rowBlock + mA1) * lda + akbase + ksA1 * 4;
    // B loads: k = idx>>5, ns = idx&31
    const int kB0 = tid >> 5,          nsB0 = tid & 31;
    const int kB1 = (tid + 256) >> 5,  nsB1 = tid & 31;
    const float *pB0, *pB1, *pB0b = nullptr, *pB1b = nullptr;
    if (MODE == 2) {
        pB0  = Bp + (size_t)(e0 * SUBH + kB0) * Dc + colBlock + nsB0 * 4;
        pB1  = Bp + (size_t)(e0 * SUBH + kB1) * Dc + colBlock + nsB1 * 4;
        pB0b = Bp + (size_t)(e1 * SUBH + kB0) * Dc + colBlock + nsB0 * 4;
        pB1b = Bp + (size_t)(e1 * SUBH + kB1) * Dc + colBlock + nsB1 * 4;
    } else {
        pB0 = Bp + (size_t)kB0 * ldn + colBlock + nsB0 * 4;
        pB1 = Bp + (size_t)kB1 * ldn + colBlock + nsB1 * 4;
    }
    const size_t stepB = (size_t)16 * ((MODE == 2) ? Dc : ldn);

    // smem store pointers (stage 0 base; add STAGE_E for stage 1)
    __half* sA0 = smem + mA0 * AROWE + ksA0 * 4;
    __half* sA1 = smem + mA1 * AROWE + ksA1 * 4;
    __half* sB0 = smem + ABLK + kB0 * BROWE + nsB0 * 4;
    __half* sB1 = smem + ABLK + kB1 * BROWE + nsB1 * 4;
    // fragment base pointers
    const __half* fA = smem + (wm * 32) * AROWE;
    const __half* fB = smem + ABLK + wn * 64;

    wmma::fragment<wmma::accumulator, 16, 16, 16, float> acc[2][4];
#pragma unroll
    for (int mt = 0; mt < 2; mt++)
#pragma unroll
        for (int nt = 0; nt < 4; nt++) wmma::fill_fragment(acc[mt][nt], 0.0f);

    float4 pa[2], pb[2];

    auto loadRegs = [&](int c) {
        const size_t aoff = (size_t)c * 16;
        pa[0] = *(const float4*)(pA0 + aoff);
        pa[1] = *(const float4*)(pA1 + aoff);
        if (MODE == 2) {
            if (c < 32) {
                const size_t boff = (size_t)c * stepB;
                pb[0] = *(const float4*)(pB0 + boff);
                pb[1] = *(const float4*)(pB1 + boff);
            } else {
                const size_t boff = (size_t)(c - 32) * stepB;
                pb[0] = *(const float4*)(pB0b + boff);
                pb[1] = *(const float4*)(pB1b + boff);
            }
        } else {
            const size_t boff = (size_t)c * stepB;
            pb[0] = *(const float4*)(pB0 + boff);
            pb[1] = *(const float4*)(pB1 + boff);
        }
    };

    auto convStore = [&](int st) {
        const int so = st * STAGE_E;
#pragma unroll
        for (int j = 0; j < 2; j++) {
            // A: fp16 hi + residual lo (packed conversions)
            const float4 v = pa[j];
            const __half2 h01 = __float22half2_rn(make_float2(v.x, v.y));
            const __half2 h23 = __float22half2_rn(make_float2(v.z, v.w));
            const float2 f01 = __half22float2(h01);
            const float2 f23 = __half22float2(h23);
            const __half2 l01 = __float22half2_rn(make_float2(v.x - f01.x, v.y - f01.y));
            const __half2 l23 = __float22half2_rn(make_float2(v.z - f23.x, v.w - f23.y));
            __half* sa = (j == 0 ? sA0 : sA1) + so;
            uint2 hv, lv;
            hv.x = *(const uint32_t*)&h01; hv.y = *(const uint32_t*)&h23;
            lv.x = *(const uint32_t*)&l01; lv.y = *(const uint32_t*)&l23;
            *(uint2*)(sa)      = hv;
            *(uint2*)(sa + 16) = lv;

            // B: single fp16
            const float4 u = pb[j];
            const __half2 b01 = __float22half2_rn(make_float2(u.x, u.y));
            const __half2 b23 = __float22half2_rn(make_float2(u.z, u.w));
            uint2 bv;
            bv.x = *(const uint32_t*)&b01; bv.y = *(const uint32_t*)&b23;
            *(uint2*)((j == 0 ? sB0 : sB1) + so) = bv;
        }
    };

    // prologue
    loadRegs(0);
    convStore(0);
    __syncthreads();

    for (int c = 0; c < nstages; c++) {
        if (c + 1 < nstages) loadRegs(c + 1);

        const int so = (c & 1) * STAGE_E;
        wmma::fragment<wmma::matrix_a, 16, 16, 16, __half, wmma::row_major> ah[2], al[2];
#pragma unroll
        for (int mt = 0; mt < 2; mt++) {
            const __half* ab = fA + so + mt * 16 * AROWE;
            wmma::load_matrix_sync(ah[mt], ab, AROWE);
            wmma::load_matrix_sync(al[mt], ab + 16, AROWE);
        }
#pragma unroll
        for (int nt = 0; nt < 4; nt++) {
            wmma::fragment<wmma::matrix_b, 16, 16, 16, __half, wmma::row_major> bf;
            wmma::load_matrix_sync(bf, fB + so + nt * 16, BROWE);
#pragma unroll
            for (int mt = 0; mt < 2; mt++) {
                wmma::mma_sync(acc[mt][nt], ah[mt], bf, acc[mt][nt]);
                wmma::mma_sync(acc[mt][nt], al[mt], bf, acc[mt][nt]);
            }
        }

        if (c + 1 < nstages) convStore((c + 1) & 1);
        __syncthreads();
    }

    // ---- epilogue (R10-proven) ----
    float* scr = (float*)smem + warp * (16 * 68);
    const int srow = lane >> 1;
    const int cb = (lane & 1) * 32;

#pragma unroll
    for (int mt = 0; mt < 2; mt++) {
#pragma unroll
        for (int nt = 0; nt < 4; nt++)
            wmma::store_matrix_sync(scr + nt * 16, acc[mt][nt], 68, wmma::mem_row_major);
        __syncwarp();

        const int grow = rowBlock + wm * 32 + mt * 16 + srow;
        const int gcol0 = colBlock + wn * 64 + cb;

        if (MODE == 2) {
            float* orow = outp + (size_t)(z * Sc + grow) * Dc + gcol0;
#pragma unroll
            for (int cc = 0; cc < 32; cc += 2) {
                const float v0 = scr[srow * 68 + cb + cc]     + bias[gcol0 + cc];
                const float v1 = scr[srow * 68 + cb + cc + 1] + bias[gcol0 + cc + 1];
                *(float2*)(orow + cc) = make_float2(v0, v1);
            }
        } else {
            float* dst;
            if (MODE == 0) {
                dst = g_h1 + (size_t)(z * Sc + grow) * SUBH + gcol0;
            } else {
                dst = g_gsel + (size_t)((z >> 1) * Sc + grow) * (2 * SUBH)
                    + (z & 1) * SUBH + gcol0;
            }
#pragma unroll
            for (int cc = 0; cc < 32; cc += 2) {
                const float g0 = gelu_exact(scr[srow * 68 + cb + cc]     + bias[gcol0 + cc]);
                const float g1 = gelu_exact(scr[srow * 68 + cb + cc + 1] + bias[gcol0 + cc + 1]);
                *(float2*)(dst + cc) = make_float2(g0, g1);
            }
        }
        __syncwarp();
    }
}

// ============================================================
extern "C" void kernel_launch(void* const* d_in, const int* in_sizes, int n_in,
                              void* d_out, int out_size) {
    const float* x        = (const float*)d_in[0];
    const float* w_switch = (const float*)d_in[1];
    const float* b_switch = (const float*)d_in[2];
    const float* w1       = (const float*)d_in[3];
    const float* b1       = (const float*)d_in[4];
    const float* w2       = (const float*)d_in[5];
    const float* b2       = (const float*)d_in[6];
    const float* w_out    = (const float*)d_in[7];
    const float* b_out    = (const float*)d_in[8];
    float* out = (float*)d_out;

    // 1) routing (proven)
    route_partial_kernel<<<NCHUNKR, 256>>>(x, w_switch);
    route_topk_kernel<<<1, 64>>>(b_switch);

    // 2) fp16 2-term WMMA expert MLP (R10 shape + hoisted addressing)
    conv_wmma_gemm<0><<<dim3(SUBH / 128, Sc / 128, 16), 256, SMEM_ALLOC>>>(x, w1, b1, nullptr);
    conv_wmma_gemm<1><<<dim3(SUBH / 128, Sc / 128, 16), 256, SMEM_ALLOC>>>(nullptr, w2, b2, nullptr);
    conv_wmma_gemm<2><<<dim3(Dc / 128, Sc / 128, Bc), 256, SMEM_ALLOC>>>(nullptr, w_out, b_out, out);
}

// round 14
// speedup vs baseline: 1.3308x; 1.2308x over previous
#include <cuda_runtime.h>
#include <cuda_fp16.h>
#include <mma.h>
#include <math.h>
#include <stdint.h>

using namespace nvcuda;

#define Bc 8
#define Sc 2048
#define Dc 1024
#define Ec 8
#define SUBD 128
#define SUBH 512
#define SD (Sc*Dc)
#define NCHUNKR 256
#define CHUNKR (SD/NCHUNKR)

// ---------------- scratch (static device globals) ----------------
__device__ float g_h1[16*Sc*SUBH];
__device__ __align__(16) __half g_g16[(long)Bc*Sc*2*SUBH];   // fp16 concat g
__device__ float g_part[NCHUNKR*Bc*Ec];
__device__ int   g_sel[Bc*2];

__device__ __forceinline__ float gelu_exact(float v) {
    return 0.5f * v * (1.0f + erff(v * 0.70710678118654752440f));
}

// ============================================================
// Routing (R1 verbatim — proven)
// ============================================================
__global__ void route_partial_kernel(const float* __restrict__ x,
                                     const float* __restrict__ w) {
    const int chunk = blockIdx.x;
    const int tid   = threadIdx.x;

    float acc[Bc][Ec];
#pragma unroll
    for (int b = 0; b < Bc; b++)
#pragma unroll
        for (int e = 0; e < Ec; e++) acc[b][e] = 0.f;

    const long base = (long)chunk * CHUNKR;
    for (int it = 0; it < CHUNKR / 256; it++) {
        const long i = base + it * 256 + tid;
        const float4 w0 = *(const float4*)(w + i * 8);
        const float4 w1v = *(const float4*)(w + i * 8 + 4);
        const float wv[8] = {w0.x, w0.y, w0.z, w0.w, w1v.x, w1v.y, w1v.z, w1v.w};
#pragma unroll
        for (int b = 0; b < Bc; b++) {
            const float xv = x[(long)b * SD + i];
#pragma unroll
            for (int e = 0; e < Ec; e++) acc[b][e] = fmaf(xv, wv[e], acc[b][e]);
        }
    }

    __shared__ float sm[8][64];
    const int lane = tid & 31, warp = tid >> 5;
#pragma unroll
    for (int b = 0; b < Bc; b++) {
#pragma unroll
        for (int e = 0; e < Ec; e++) {
            float v = acc[b][e];
#pragma unroll
            for (int o = 16; o > 0; o >>= 1) v += __shfl_down_sync(0xffffffffu, v, o);
            if (lane == 0) sm[warp][b * 8 + e] = v;
        }
    }
    __syncthreads();
    if (tid < 64) {
        float s = 0.f;
#pragma unroll
        for (int w2 = 0; w2 < 8; w2++) s += sm[w2][tid];
        g_part[chunk * 64 + tid] = s;
    }
}

__global__ void route_topk_kernel(const float* __restrict__ b_switch) {
    __shared__ float lg[64];
    const int t = threadIdx.x;
    float s = b_switch[t & 7];
    for (int c = 0; c < NCHUNKR; c++) s += g_part[c * 64 + t];
    lg[t] = s;
    __syncthreads();
    if (t < Bc) {
        const float* L = lg + t * 8;
        int i0 = 0; float v0 = L[0];
#pragma unroll
        for (int e = 1; e < 8; e++) if (L[e] > v0) { v0 = L[e]; i0 = e; }
        int i1 = -1; float v1 = -3.0e38f;
#pragma unroll
        for (int e = 0; e < 8; e++) if (e != i0 && L[e] > v1) { v1 = L[e]; i1 = e; }
        g_sel[t * 2 + 0] = i0;
        g_sel[t * 2 + 1] = i1;
    }
}

// ============================================================
// WMMA fp16 GEMM family (R10-proven structure; strides 40/136 are
// conflict-free per LDSM 8-row phase analysis).
// MODE 0: g_h1 = gelu(x[:, e*128:+128] @ w1[e] + b1[e])  A fp32 2-term
// MODE 1: g_g16= gelu(g_h1 @ w2[e] + b2[e])              A fp32 2-term, fp16 out
// MODE 2: out  = g_g16 @ gather(w_out) + b_out           A fp16 1-term
// ============================================================
#define AROWE 40
#define ABLK  (128*AROWE)
#define BROWE 136
#define BBLK  (16*BROWE)
#define STAGE_E (ABLK + BBLK)
#define SMEM_ALLOC 34816

__device__ __forceinline__ uint32_t pack_h2(float a, float b) {
    __half2 h; h.x = __float2half_rn(a); h.y = __float2half_rn(b);
    return *(uint32_t*)&h;
}

template <int MODE>
__global__ void __launch_bounds__(256)
conv_wmma_gemm(const float* __restrict__ A0, const float* __restrict__ B0,
               const float* __restrict__ bias0, float* __restrict__ outp) {
    extern __shared__ __half smem[];

    const int tid = threadIdx.x;
    const int z = blockIdx.z;
    const int rowBlock = blockIdx.y * 128;
    const int colBlock = blockIdx.x * 128;
    const int warp = tid >> 5, lane = tid & 31;
    const int wm = warp & 3, wn = warp >> 2;

    const float* A = nullptr;
    const float* Bp;
    const float* bias;
    int lda = 0, ldn, akbase = 0, nstages, e0 = 0, e1 = 0;
    if (MODE == 0) {
        const int e = g_sel[z];
        A = A0 + (size_t)(z >> 1) * SD; lda = Dc; akbase = e * SUBD;
        Bp = B0 + (size_t)e * SUBD * SUBH; ldn = SUBH;
        bias = bias0 + e * SUBH;
        nstages = SUBD / 16;
    } else if (MODE == 1) {
        const int e = g_sel[z];
        A = g_h1 + (size_t)z * Sc * SUBH; lda = SUBH; akbase = 0;
        Bp = B0 + (size_t)e * SUBH * SUBH; ldn = SUBH;
        bias = bias0 + e * SUBH;
        nstages = SUBH / 16;
    } else {
        Bp = B0; ldn = Dc;
        bias = bias0;
        nstages = (2 * SUBH) / 16;
        e0 = g_sel[z * 2]; e1 = g_sel[z * 2 + 1];
    }
    const __half* A16 = (MODE == 2) ? (g_g16 + (size_t)z * Sc * (2 * SUBH)) : nullptr;

    wmma::fragment<wmma::accumulator, 16, 16, 16, float> acc[2][4];
#pragma unroll
    for (int mt = 0; mt < 2; mt++)
#pragma unroll
        for (int nt = 0; nt < 4; nt++) wmma::fill_fragment(acc[mt][nt], 0.0f);

    float4 pa[2], pb[2];
    uint4 pah;                    // MODE 2: fp16 A, 8 halfs per thread

    auto loadRegs = [&](int c) {
        const int bk0 = c * 16;
        if (MODE == 2) {
            // A fp16: 128 rows x 16 halfs = 4KB; 256 thr x 16B
            const int m = tid >> 1, seg = tid & 1;
            pah = *(const uint4*)(A16 + (size_t)(rowBlock + m) * (2 * SUBH)
                                  + c * 16 + seg * 8);
        } else {
            const int ak0 = akbase + c * 16;
#pragma unroll
            for (int j = 0; j < 2; j++) {
                const int idx = tid + j * 256;
                const int m = idx >> 2, ks = idx & 3;
                pa[j] = *(const float4*)(A + (size_t)(rowBlock + m) * lda + ak0 + ks * 4);
            }
        }
#pragma unroll
        for (int j = 0; j < 2; j++) {
            const int idx = tid + j * 256;
            const int k = idx >> 5, ns = idx & 31;
            const int kg = bk0 + k;
            const float* brow;
            if (MODE == 2) {
                const int r = (kg < SUBH) ? (e0 * SUBH + kg) : (e1 * SUBH + kg - SUBH);
                brow = Bp + (size_t)r * Dc;
            } else {
                brow = Bp + (size_t)kg * ldn;
            }
            pb[j] = *(const float4*)(brow + colBlock + ns * 4);
        }
    };

    auto convStore = [&](int st) {
        __half* s = smem + st * STAGE_E;
        if (MODE == 2) {
            const int m = tid >> 1, seg = tid & 1;
            *(uint4*)(s + m * AROWE + seg * 8) = pah;   // hi slot; lo unused
        } else {
#pragma unroll
            for (int j = 0; j < 2; j++) {
                const int idx = tid + j * 256;
                const int m = idx >> 2, ks = idx & 3;
                const float4 v = pa[j];
                const float hx = __half2float(__float2half_rn(v.x));
                const float hy = __half2float(__float2half_rn(v.y));
                const float hz = __half2float(__float2half_rn(v.z));
                const float hw = __half2float(__float2half_rn(v.w));
                uint2 hi, lo;
                hi.x = pack_h2(v.x, v.y);           hi.y = pack_h2(v.z, v.w);
                lo.x = pack_h2(v.x - hx, v.y - hy); lo.y = pack_h2(v.z - hz, v.w - hw);
                *(uint2*)(s + m * AROWE + ks * 4)      = hi;
                *(uint2*)(s + m * AROWE + 16 + ks * 4) = lo;
            }
        }
#pragma unroll
        for (int j = 0; j < 2; j++) {
            const int idx = tid + j * 256;
            const int k = idx >> 5, ns = idx & 31;
            const float4 v = pb[j];
            uint2 hv;
            hv.x = pack_h2(v.x, v.y); hv.y = pack_h2(v.z, v.w);
            *(uint2*)(s + ABLK + k * BROWE + ns * 4) = hv;
        }
    };

    // prologue: fill stage 0
    loadRegs(0);
    convStore(0);
    __syncthreads();

    for (int c = 0; c < nstages; c++) {
        if (c + 1 < nstages) loadRegs(c + 1);

        const __half* s = smem + (c & 1) * STAGE_E;
        wmma::fragment<wmma::matrix_a, 16, 16, 16, __half, wmma::row_major> ah[2], al[2];
#pragma unroll
        for (int mt = 0; mt < 2; mt++) {
            const __half* ab = s + (wm * 32 + mt * 16) * AROWE;
            wmma::load_matrix_sync(ah[mt], ab, AROWE);
            if (MODE != 2) wmma::load_matrix_sync(al[mt], ab + 16, AROWE);
        }
#pragma unroll
        for (int nt = 0; nt < 4; nt++) {
            wmma::fragment<wmma::matrix_b, 16, 16, 16, __half, wmma::row_major> bf;
            wmma::load_matrix_sync(bf, s + ABLK + (wn * 64 + nt * 16), BROWE);
#pragma unroll
            for (int mt = 0; mt < 2; mt++) {
                wmma::mma_sync(acc[mt][nt], ah[mt], bf, acc[mt][nt]);
                if (MODE != 2) wmma::mma_sync(acc[mt][nt], al[mt], bf, acc[mt][nt]);
            }
        }

        if (c + 1 < nstages) convStore((c + 1) & 1);
        __syncthreads();
    }

    // ---- epilogue ----
    float* scr = (float*)smem + warp * (16 * 68);
    const int srow = lane >> 1;
    const int cb = (lane & 1) * 32;

#pragma unroll
    for (int mt = 0; mt < 2; mt++) {
#pragma unroll
        for (int nt = 0; nt < 4; nt++)
            wmma::store_matrix_sync(scr + nt * 16, acc[mt][nt], 68, wmma::mem_row_major);
        __syncwarp();

        const int grow = rowBlock + wm * 32 + mt * 16 + srow;
        const int gcol0 = colBlock + wn * 64 + cb;

        if (MODE == 2) {
            float* orow = outp + (size_t)(z * Sc + grow) * Dc + gcol0;
#pragma unroll
            for (int cc = 0; cc < 32; cc += 2) {
                const float v0 = scr[srow * 68 + cb + cc]     + bias[gcol0 + cc];
                const float v1 = scr[srow * 68 + cb + cc + 1] + bias[gcol0 + cc + 1];
                *(float2*)(orow + cc) = make_float2(v0, v1);
            }
        } else if (MODE == 0) {
            float* dst = g_h1 + (size_t)(z * Sc + grow) * SUBH + gcol0;
#pragma unroll
            for (int cc = 0; cc < 32; cc += 2) {
                const float g0 = gelu_exact(scr[srow * 68 + cb + cc]     + bias[gcol0 + cc]);
                const float g1 = gelu_exact(scr[srow * 68 + cb + cc + 1] + bias[gcol0 + cc + 1]);
                *(float2*)(dst + cc) = make_float2(g0, g1);
            }
        } else {
            // MODE 1: write fp16 g directly (consumed by MODE 2)
            __half* dst = g_g16 + (size_t)((z >> 1) * Sc + grow) * (2 * SUBH)
                        + (z & 1) * SUBH + gcol0;
#pragma unroll
            for (int cc = 0; cc < 32; cc += 2) {
                const float g0 = gelu_exact(scr[srow * 68 + cb + cc]     + bias[gcol0 + cc]);
                const float g1 = gelu_exact(scr[srow * 68 + cb + cc + 1] + bias[gcol0 + cc + 1]);
                *(__half2*)(dst + cc) = __float22half2_rn(make_float2(g0, g1));
            }
        }
        __syncwarp();
    }
}

// ============================================================
extern "C" void kernel_launch(void* const* d_in, const int* in_sizes, int n_in,
                              void* d_out, int out_size) {
    const float* x        = (const float*)d_in[0];
    const float* w_switch = (const float*)d_in[1];
    const float* b_switch = (const float*)d_in[2];
    const float* w1       = (const float*)d_in[3];
    const float* b1       = (const float*)d_in[4];
    const float* w2       = (const float*)d_in[5];
    const float* b2       = (const float*)d_in[6];
    const float* w_out    = (const float*)d_in[7];
    const float* b_out    = (const float*)d_in[8];
    float* out = (float*)d_out;

    // 1) routing (proven)
    route_partial_kernel<<<NCHUNKR, 256>>>(x, w_switch);
    route_topk_kernel<<<1, 64>>>(b_switch);

    // 2) fp16 WMMA expert MLP (R10 structure; mode-2 single-term fp16 A)
    conv_wmma_gemm<0><<<dim3(SUBH / 128, Sc / 128, 16), 256, SMEM_ALLOC>>>(x, w1, b1, nullptr);
    conv_wmma_gemm<1><<<dim3(SUBH / 128, Sc / 128, 16), 256, SMEM_ALLOC>>>(nullptr, w2, b2, nullptr);
    conv_wmma_gemm<2><<<dim3(Dc / 128, Sc / 128, Bc), 256, SMEM_ALLOC>>>(nullptr, w_out, b_out, out);
}

// round 15
// speedup vs baseline: 1.4677x; 1.1029x over previous
#include <cuda_runtime.h>
#include <cuda_fp16.h>
#include <mma.h>
#include <math.h>
#include <stdint.h>

using namespace nvcuda;

#define Bc 8
#define Sc 2048
#define Dc 1024
#define Ec 8
#define SUBD 128
#define SUBH 512
#define SD (Sc*Dc)
#define NCHUNKR 256
#define CHUNKR (SD/NCHUNKR)

// ---------------- scratch (static device globals) ----------------
__device__ __align__(16) __half g_h16[16*Sc*SUBH];           // fp16 h1
__device__ __align__(16) __half g_g16[(long)Bc*Sc*2*SUBH];   // fp16 concat g
__device__ float g_part[NCHUNKR*Bc*Ec];
__device__ int   g_sel[Bc*2];

__device__ __forceinline__ float gelu_exact(float v) {
    return 0.5f * v * (1.0f + erff(v * 0.70710678118654752440f));
}

// ============================================================
// Routing (R1 verbatim — proven)
// ============================================================
__global__ void route_partial_kernel(const float* __restrict__ x,
                                     const float* __restrict__ w) {
    const int chunk = blockIdx.x;
    const int tid   = threadIdx.x;

    float acc[Bc][Ec];
#pragma unroll
    for (int b = 0; b < Bc; b++)
#pragma unroll
        for (int e = 0; e < Ec; e++) acc[b][e] = 0.f;

    const long base = (long)chunk * CHUNKR;
    for (int it = 0; it < CHUNKR / 256; it++) {
        const long i = base + it * 256 + tid;
        const float4 w0 = *(const float4*)(w + i * 8);
        const float4 w1v = *(const float4*)(w + i * 8 + 4);
        const float wv[8] = {w0.x, w0.y, w0.z, w0.w, w1v.x, w1v.y, w1v.z, w1v.w};
#pragma unroll
        for (int b = 0; b < Bc; b++) {
            const float xv = x[(long)b * SD + i];
#pragma unroll
            for (int e = 0; e < Ec; e++) acc[b][e] = fmaf(xv, wv[e], acc[b][e]);
        }
    }

    __shared__ float sm[8][64];
    const int lane = tid & 31, warp = tid >> 5;
#pragma unroll
    for (int b = 0; b < Bc; b++) {
#pragma unroll
        for (int e = 0; e < Ec; e++) {
            float v = acc[b][e];
#pragma unroll
            for (int o = 16; o > 0; o >>= 1) v += __shfl_down_sync(0xffffffffu, v, o);
            if (lane == 0) sm[warp][b * 8 + e] = v;
        }
    }
    __syncthreads();
    if (tid < 64) {
        float s = 0.f;
#pragma unroll
        for (int w2 = 0; w2 < 8; w2++) s += sm[w2][tid];
        g_part[chunk * 64 + tid] = s;
    }
}

__global__ void route_topk_kernel(const float* __restrict__ b_switch) {
    __shared__ float lg[64];
    const int t = threadIdx.x;
    float s = b_switch[t & 7];
    for (int c = 0; c < NCHUNKR; c++) s += g_part[c * 64 + t];
    lg[t] = s;
    __syncthreads();
    if (t < Bc) {
        const float* L = lg + t * 8;
        int i0 = 0; float v0 = L[0];
#pragma unroll
        for (int e = 1; e < 8; e++) if (L[e] > v0) { v0 = L[e]; i0 = e; }
        int i1 = -1; float v1 = -3.0e38f;
#pragma unroll
        for (int e = 0; e < 8; e++) if (e != i0 && L[e] > v1) { v1 = L[e]; i1 = e; }
        g_sel[t * 2 + 0] = i0;
        g_sel[t * 2 + 1] = i1;
    }
}

// ============================================================
// WMMA fp16 GEMM family (R10/R14-proven structure).
// MODE 0: g_h16 = gelu(x[:, e*128:+128] @ w1[e] + b1[e])  A fp32 2-term -> fp16 out
// MODE 1: g_g16 = gelu(g_h16 @ w2[e] + b2[e])             A fp16 1-term -> fp16 out
// MODE 2: out   = g_g16 @ gather(w_out) + b_out           A fp16 1-term -> fp32 out
// ============================================================
#define AROWE 40
#define ABLK  (128*AROWE)
#define BROWE 136
#define BBLK  (16*BROWE)
#define STAGE_E (ABLK + BBLK)
#define SMEM_ALLOC 34816

__device__ __forceinline__ uint32_t pack_h2(float a, float b) {
    __half2 h; h.x = __float2half_rn(a); h.y = __float2half_rn(b);
    return *(uint32_t*)&h;
}

template <int MODE>
__global__ void __launch_bounds__(256)
conv_wmma_gemm(const float* __restrict__ A0, const float* __restrict__ B0,
               const float* __restrict__ bias0, float* __restrict__ outp) {
    extern __shared__ __half smem[];

    const int tid = threadIdx.x;
    const int z = blockIdx.z;
    const int rowBlock = blockIdx.y * 128;
    const int colBlock = blockIdx.x * 128;
    const int warp = tid >> 5, lane = tid & 31;
    const int wm = warp & 3, wn = warp >> 2;

    constexpr bool A_IS_FP16 = (MODE >= 1);

    const float* A = nullptr;
    const __half* A16 = nullptr;
    const float* Bp;
    const float* bias;
    int lda = 0, ldn, akbase = 0, nstages, e0 = 0, e1 = 0;
    if (MODE == 0) {
        const int e = g_sel[z];
        A = A0 + (size_t)(z >> 1) * SD; lda = Dc; akbase = e * SUBD;
        Bp = B0 + (size_t)e * SUBD * SUBH; ldn = SUBH;
        bias = bias0 + e * SUBH;
        nstages = SUBD / 16;
    } else if (MODE == 1) {
        const int e = g_sel[z];
        A16 = g_h16 + (size_t)z * Sc * SUBH; lda = SUBH;
        Bp = B0 + (size_t)e * SUBH * SUBH; ldn = SUBH;
        bias = bias0 + e * SUBH;
        nstages = SUBH / 16;
    } else {
        A16 = g_g16 + (size_t)z * Sc * (2 * SUBH); lda = 2 * SUBH;
        Bp = B0; ldn = Dc;
        bias = bias0;
        nstages = (2 * SUBH) / 16;
        e0 = g_sel[z * 2]; e1 = g_sel[z * 2 + 1];
    }

    wmma::fragment<wmma::accumulator, 16, 16, 16, float> acc[2][4];
#pragma unroll
    for (int mt = 0; mt < 2; mt++)
#pragma unroll
        for (int nt = 0; nt < 4; nt++) wmma::fill_fragment(acc[mt][nt], 0.0f);

    float4 pa[2], pb[2];
    uint4 pah;                    // fp16 A: 8 halfs per thread

    auto loadRegs = [&](int c) {
        const int bk0 = c * 16;
        if (A_IS_FP16) {
            const int m = tid >> 1, seg = tid & 1;
            pah = *(const uint4*)(A16 + (size_t)(rowBlock + m) * lda + c * 16 + seg * 8);
        } else {
            const int ak0 = akbase + c * 16;
#pragma unroll
            for (int j = 0; j < 2; j++) {
                const int idx = tid + j * 256;
                const int m = idx >> 2, ks = idx & 3;
                pa[j] = *(const float4*)(A + (size_t)(rowBlock + m) * lda + ak0 + ks * 4);
            }
        }
#pragma unroll
        for (int j = 0; j < 2; j++) {
            const int idx = tid + j * 256;
            const int k = idx >> 5, ns = idx & 31;
            const int kg = bk0 + k;
            const float* brow;
            if (MODE == 2) {
                const int r = (kg < SUBH) ? (e0 * SUBH + kg) : (e1 * SUBH + kg - SUBH);
                brow = Bp + (size_t)r * Dc;
            } else {
                brow = Bp + (size_t)kg * ldn;
            }
            pb[j] = *(const float4*)(brow + colBlock + ns * 4);
        }
    };

    auto convStore = [&](int st) {
        __half* s = smem + st * STAGE_E;
        if (A_IS_FP16) {
            const int m = tid >> 1, seg = tid & 1;
            *(uint4*)(s + m * AROWE + seg * 8) = pah;   // hi slot; lo unused
        } else {
#pragma unroll
            for (int j = 0; j < 2; j++) {
                const int idx = tid + j * 256;
                const int m = idx >> 2, ks = idx & 3;
                const float4 v = pa[j];
                const float hx = __half2float(__float2half_rn(v.x));
                const float hy = __half2float(__float2half_rn(v.y));
                const float hz = __half2float(__float2half_rn(v.z));
                const float hw = __half2float(__float2half_rn(v.w));
                uint2 hi, lo;
                hi.x = pack_h2(v.x, v.y);           hi.y = pack_h2(v.z, v.w);
                lo.x = pack_h2(v.x - hx, v.y - hy); lo.y = pack_h2(v.z - hz, v.w - hw);
                *(uint2*)(s + m * AROWE + ks * 4)      = hi;
                *(uint2*)(s + m * AROWE + 16 + ks * 4) = lo;
            }
        }
#pragma unroll
        for (int j = 0; j < 2; j++) {
            const int idx = tid + j * 256;
            const int k = idx >> 5, ns = idx & 31;
            const float4 v = pb[j];
            uint2 hv;
            hv.x = pack_h2(v.x, v.y); hv.y = pack_h2(v.z, v.w);
            *(uint2*)(s + ABLK + k * BROWE + ns * 4) = hv;
        }
    };

    // prologue: fill stage 0
    loadRegs(0);
    convStore(0);
    __syncthreads();

    for (int c = 0; c < nstages; c++) {
        if (c + 1 < nstages) loadRegs(c + 1);

        const __half* s = smem + (c & 1) * STAGE_E;
        wmma::fragment<wmma::matrix_a, 16, 16, 16, __half, wmma::row_major> ah[2], al[2];
#pragma unroll
        for (int mt = 0; mt < 2; mt++) {
            const __half* ab = s + (wm * 32 + mt * 16) * AROWE;
            wmma::load_matrix_sync(ah[mt], ab, AROWE);
            if (!A_IS_FP16) wmma::load_matrix_sync(al[mt], ab + 16, AROWE);
        }
#pragma unroll
        for (int nt = 0; nt < 4; nt++) {
            wmma::fragment<wmma::matrix_b, 16, 16, 16, __half, wmma::row_major> bf;
            wmma::load_matrix_sync(bf, s + ABLK + (wn * 64 + nt * 16), BROWE);
#pragma unroll
            for (int mt = 0; mt < 2; mt++) {
                wmma::mma_sync(acc[mt][nt], ah[mt], bf, acc[mt][nt]);
                if (!A_IS_FP16) wmma::mma_sync(acc[mt][nt], al[mt], bf, acc[mt][nt]);
            }
        }

        if (c + 1 < nstages) convStore((c + 1) & 1);
        __syncthreads();
    }

    // ---- epilogue ----
    float* scr = (float*)smem + warp * (16 * 68);
    const int srow = lane >> 1;
    const int cb = (lane & 1) * 32;

#pragma unroll
    for (int mt = 0; mt < 2; mt++) {
#pragma unroll
        for (int nt = 0; nt < 4; nt++)
            wmma::store_matrix_sync(scr + nt * 16, acc[mt][nt], 68, wmma::mem_row_major);
        __syncwarp();

        const int grow = rowBlock + wm * 32 + mt * 16 + srow;
        const int gcol0 = colBlock + wn * 64 + cb;

        if (MODE == 2) {
            float* orow = outp + (size_t)(z * Sc + grow) * Dc + gcol0;
#pragma unroll
            for (int cc = 0; cc < 32; cc += 2) {
                const float v0 = scr[srow * 68 + cb + cc]     + bias[gcol0 + cc];
                const float v1 = scr[srow * 68 + cb + cc + 1] + bias[gcol0 + cc + 1];
                *(float2*)(orow + cc) = make_float2(v0, v1);
            }
        } else {
            __half* dst;
            if (MODE == 0) {
                dst = g_h16 + (size_t)(z * Sc + grow) * SUBH + gcol0;
            } else {
                dst = g_g16 + (size_t)((z >> 1) * Sc + grow) * (2 * SUBH)
                    + (z & 1) * SUBH + gcol0;
            }
#pragma unroll
            for (int cc = 0; cc < 32; cc += 2) {
                const float g0 = gelu_exact(scr[srow * 68 + cb + cc]     + bias[gcol0 + cc]);
                const float g1 = gelu_exact(scr[srow * 68 + cb + cc + 1] + bias[gcol0 + cc + 1]);
                *(__half2*)(dst + cc) = __float22half2_rn(make_float2(g0, g1));
            }
        }
        __syncwarp();
    }
}

// ============================================================
extern "C" void kernel_launch(void* const* d_in, const int* in_sizes, int n_in,
                              void* d_out, int out_size) {
    const float* x        = (const float*)d_in[0];
    const float* w_switch = (const float*)d_in[1];
    const float* b_switch = (const float*)d_in[2];
    const float* w1       = (const float*)d_in[3];
    const float* b1       = (const float*)d_in[4];
    const float* w2       = (const float*)d_in[5];
    const float* b2       = (const float*)d_in[6];
    const float* w_out    = (const float*)d_in[7];
    const float* b_out    = (const float*)d_in[8];
    float* out = (float*)d_out;

    // 1) routing (proven)
    route_partial_kernel<<<NCHUNKR, 256>>>(x, w_switch);
    route_topk_kernel<<<1, 64>>>(b_switch);

    // 2) fp16 WMMA expert MLP (modes 1 & 2 single-term fp16 A)
    conv_wmma_gemm<0><<<dim3(SUBH / 128, Sc / 128, 16), 256, SMEM_ALLOC>>>(x, w1, b1, nullptr);
    conv_wmma_gemm<1><<<dim3(SUBH / 128, Sc / 128, 16), 256, SMEM_ALLOC>>>(nullptr, w2, b2, nullptr);
    conv_wmma_gemm<2><<<dim3(Dc / 128, Sc / 128, Bc), 256, SMEM_ALLOC>>>(nullptr, w_out, b_out, out);
}

// round 16
// speedup vs baseline: 1.4959x; 1.0192x over previous
#include <cuda_runtime.h>
#include <cuda_fp16.h>
#include <mma.h>
#include <math.h>
#include <stdint.h>

using namespace nvcuda;

#define Bc 8
#define Sc 2048
#define Dc 1024
#define Ec 8
#define SUBD 128
#define SUBH 512
#define SD (Sc*Dc)
#define NCHUNKR 256
#define CHUNKR (SD/NCHUNKR)

// ---------------- scratch (static device globals) ----------------
__device__ __align__(16) __half g_h16[16*Sc*SUBH];           // fp16 h1
__device__ __align__(16) __half g_g16[(long)Bc*Sc*2*SUBH];   // fp16 concat g
__device__ __align__(16) __half g_w116[Ec*SUBD*SUBH];        // fp16 w1 [e][k][n]
__device__ __align__(16) __half g_w216[Ec*SUBH*SUBH];        // fp16 w2 [e][k][n]
__device__ __align__(16) __half g_wo16[4096*Dc];             // fp16 w_out [k][n]
__device__ float g_part[NCHUNKR*Bc*Ec];
__device__ int   g_sel[Bc*2];

__device__ __forceinline__ float gelu_exact(float v) {
    return 0.5f * v * (1.0f + erff(v * 0.70710678118654752440f));
}
__device__ __forceinline__ uint32_t pack_h2(float a, float b) {
    __half2 h; h.x = __float2half_rn(a); h.y = __float2half_rn(b);
    return *(uint32_t*)&h;
}

// ============================================================
// Routing (R1 verbatim — proven)
// ============================================================
__global__ void route_partial_kernel(const float* __restrict__ x,
                                     const float* __restrict__ w) {
    const int chunk = blockIdx.x;
    const int tid   = threadIdx.x;

    float acc[Bc][Ec];
#pragma unroll
    for (int b = 0; b < Bc; b++)
#pragma unroll
        for (int e = 0; e < Ec; e++) acc[b][e] = 0.f;

    const long base = (long)chunk * CHUNKR;
    for (int it = 0; it < CHUNKR / 256; it++) {
        const long i = base + it * 256 + tid;
        const float4 w0 = *(const float4*)(w + i * 8);
        const float4 w1v = *(const float4*)(w + i * 8 + 4);
        const float wv[8] = {w0.x, w0.y, w0.z, w0.w, w1v.x, w1v.y, w1v.z, w1v.w};
#pragma unroll
        for (int b = 0; b < Bc; b++) {
            const float xv = x[(long)b * SD + i];
#pragma unroll
            for (int e = 0; e < Ec; e++) acc[b][e] = fmaf(xv, wv[e], acc[b][e]);
        }
    }

    __shared__ float sm[8][64];
    const int lane = tid & 31, warp = tid >> 5;
#pragma unroll
    for (int b = 0; b < Bc; b++) {
#pragma unroll
        for (int e = 0; e < Ec; e++) {
            float v = acc[b][e];
#pragma unroll
            for (int o = 16; o > 0; o >>= 1) v += __shfl_down_sync(0xffffffffu, v, o);
            if (lane == 0) sm[warp][b * 8 + e] = v;
        }
    }
    __syncthreads();
    if (tid < 64) {
        float s = 0.f;
#pragma unroll
        for (int w2 = 0; w2 < 8; w2++) s += sm[w2][tid];
        g_part[chunk * 64 + tid] = s;
    }
}

__global__ void route_topk_kernel(const float* __restrict__ b_switch) {
    __shared__ float lg[64];
    const int t = threadIdx.x;
    float s = b_switch[t & 7];
    for (int c = 0; c < NCHUNKR; c++) s += g_part[c * 64 + t];
    lg[t] = s;
    __syncthreads();
    if (t < Bc) {
        const float* L = lg + t * 8;
        int i0 = 0; float v0 = L[0];
#pragma unroll
        for (int e = 1; e < 8; e++) if (L[e] > v0) { v0 = L[e]; i0 = e; }
        int i1 = -1; float v1 = -3.0e38f;
#pragma unroll
        for (int e = 0; e < 8; e++) if (e != i0 && L[e] > v1) { v1 = L[e]; i1 = e; }
        g_sel[t * 2 + 0] = i0;
        g_sel[t * 2 + 1] = i1;
    }
}

// ============================================================
// Weight pre-convert fp32 -> fp16 (same __float2half_rn as the old
// in-loop conversion: bit-identical GEMM inputs). Pattern proven by
// the g_h16/g_g16 producer->consumer path in R14/R15.
// ============================================================
__global__ void convert_w_kernel(const float4* __restrict__ in,
                                 uint2* __restrict__ out, int n4) {
    const int i = blockIdx.x * blockDim.x + threadIdx.x;
    if (i >= n4) return;
    const float4 v = in[i];
    uint2 h;
    h.x = pack_h2(v.x, v.y);
    h.y = pack_h2(v.z, v.w);
    out[i] = h;
}

// ============================================================
// WMMA fp16 GEMM family (R15-proven structure; B now fp16 global).
// MODE 0: g_h16 = gelu(x[:, e*128:+128] @ w1[e] + b1[e])  A fp32 2-term
// MODE 1: g_g16 = gelu(g_h16 @ w2[e] + b2[e])             A fp16 1-term
// MODE 2: out   = g_g16 @ gather(w_out) + b_out           A fp16 1-term
// ============================================================
#define AROWE 40
#define ABLK  (128*AROWE)
#define BROWE 136
#define BBLK  (16*BROWE)
#define STAGE_E (ABLK + BBLK)
#define SMEM_ALLOC 34816

template <int MODE>
__global__ void __launch_bounds__(256)
conv_wmma_gemm(const float* __restrict__ A0,
               const float* __restrict__ bias0, float* __restrict__ outp) {
    extern __shared__ __half smem[];

    const int tid = threadIdx.x;
    const int z = blockIdx.z;
    const int rowBlock = blockIdx.y * 128;
    const int colBlock = blockIdx.x * 128;
    const int warp = tid >> 5, lane = tid & 31;
    const int wm = warp & 3, wn = warp >> 2;

    constexpr bool A_IS_FP16 = (MODE >= 1);

    const float* A = nullptr;
    const __half* A16 = nullptr;
    const __half* Bp16;
    const float* bias;
    int lda = 0, ldn, akbase = 0, nstages, e0 = 0, e1 = 0;
    if (MODE == 0) {
        const int e = g_sel[z];
        A = A0 + (size_t)(z >> 1) * SD; lda = Dc; akbase = e * SUBD;
        Bp16 = g_w116 + (size_t)e * SUBD * SUBH; ldn = SUBH;
        bias = bias0 + e * SUBH;
        nstages = SUBD / 16;
    } else if (MODE == 1) {
        const int e = g_sel[z];
        A16 = g_h16 + (size_t)z * Sc * SUBH; lda = SUBH;
        Bp16 = g_w216 + (size_t)e * SUBH * SUBH; ldn = SUBH;
        bias = bias0 + e * SUBH;
        nstages = SUBH / 16;
    } else {
        A16 = g_g16 + (size_t)z * Sc * (2 * SUBH); lda = 2 * SUBH;
        Bp16 = g_wo16; ldn = Dc;
        bias = bias0;
        nstages = (2 * SUBH) / 16;
        e0 = g_sel[z * 2]; e1 = g_sel[z * 2 + 1];
    }

    wmma::fragment<wmma::accumulator, 16, 16, 16, float> acc[2][4];
#pragma unroll
    for (int mt = 0; mt < 2; mt++)
#pragma unroll
        for (int nt = 0; nt < 4; nt++) wmma::fill_fragment(acc[mt][nt], 0.0f);

    float4 pa[2];
    uint4 pah;                    // fp16 A: 8 halfs per thread
    uint4 pbh;                    // fp16 B: 8 halfs per thread

    // B coords: 16 rows x 128 halfs = 256 x 16B segments
    const int kB = tid >> 4, segB = tid & 15;

    auto loadRegs = [&](int c) {
        if (A_IS_FP16) {
            const int m = tid >> 1, seg = tid & 1;
            pah = *(const uint4*)(A16 + (size_t)(rowBlock + m) * lda + c * 16 + seg * 8);
        } else {
            const int ak0 = akbase + c * 16;
#pragma unroll
            for (int j = 0; j < 2; j++) {
                const int idx = tid + j * 256;
                const int m = idx >> 2, ks = idx & 3;
                pa[j] = *(const float4*)(A + (size_t)(rowBlock + m) * lda + ak0 + ks * 4);
            }
        }
        const int kg = c * 16 + kB;
        const __half* brow;
        if (MODE == 2) {
            const int r = (kg < SUBH) ? (e0 * SUBH + kg) : (e1 * SUBH + kg - SUBH);
            brow = Bp16 + (size_t)r * Dc;
        } else {
            brow = Bp16 + (size_t)kg * ldn;
        }
        pbh = *(const uint4*)(brow + colBlock + segB * 8);
    };

    auto convStore = [&](int st) {
        __half* s = smem + st * STAGE_E;
        if (A_IS_FP16) {
            const int m = tid >> 1, seg = tid & 1;
            *(uint4*)(s + m * AROWE + seg * 8) = pah;   // hi slot; lo unused
        } else {
#pragma unroll
            for (int j = 0; j < 2; j++) {
                const int idx = tid + j * 256;
                const int m = idx >> 2, ks = idx & 3;
                const float4 v = pa[j];
                const float hx = __half2float(__float2half_rn(v.x));
                const float hy = __half2float(__float2half_rn(v.y));
                const float hz = __half2float(__float2half_rn(v.z));
                const float hw = __half2float(__float2half_rn(v.w));
                uint2 hi, lo;
                hi.x = pack_h2(v.x, v.y);           hi.y = pack_h2(v.z, v.w);
                lo.x = pack_h2(v.x - hx, v.y - hy); lo.y = pack_h2(v.z - hz, v.w - hw);
                *(uint2*)(s + m * AROWE + ks * 4)      = hi;
                *(uint2*)(s + m * AROWE + 16 + ks * 4) = lo;
            }
        }
        *(uint4*)(s + ABLK + kB * BROWE + segB * 8) = pbh;
    };

    // prologue: fill stage 0
    loadRegs(0);
    convStore(0);
    __syncthreads();

    for (int c = 0; c < nstages; c++) {
        if (c + 1 < nstages) loadRegs(c + 1);

        const __half* s = smem + (c & 1) * STAGE_E;
        wmma::fragment<wmma::matrix_a, 16, 16, 16, __half, wmma::row_major> ah[2], al[2];
#pragma unroll
        for (int mt = 0; mt < 2; mt++) {
            const __half* ab = s + (wm * 32 + mt * 16) * AROWE;
            wmma::load_matrix_sync(ah[mt], ab, AROWE);
            if (!A_IS_FP16) wmma::load_matrix_sync(al[mt], ab + 16, AROWE);
        }
#pragma unroll
        for (int nt = 0; nt < 4; nt++) {
            wmma::fragment<wmma::matrix_b, 16, 16, 16, __half, wmma::row_major> bf;
            wmma::load_matrix_sync(bf, s + ABLK + (wn * 64 + nt * 16), BROWE);
#pragma unroll
            for (int mt = 0; mt < 2; mt++) {
                wmma::mma_sync(acc[mt][nt], ah[mt], bf, acc[mt][nt]);
                if (!A_IS_FP16) wmma::mma_sync(acc[mt][nt], al[mt], bf, acc[mt][nt]);
            }
        }

        if (c + 1 < nstages) convStore((c + 1) & 1);
        __syncthreads();
    }

    // ---- epilogue ----
    float* scr = (float*)smem + warp * (16 * 68);
    const int srow = lane >> 1;
    const int cb = (lane & 1) * 32;

#pragma unroll
    for (int mt = 0; mt < 2; mt++) {
#pragma unroll
        for (int nt = 0; nt < 4; nt++)
            wmma::store_matrix_sync(scr + nt * 16, acc[mt][nt], 68, wmma::mem_row_major);
        __syncwarp();

        const int grow = rowBlock + wm * 32 + mt * 16 + srow;
        const int gcol0 = colBlock + wn * 64 + cb;

        if (MODE == 2) {
            float* orow = outp + (size_t)(z * Sc + grow) * Dc + gcol0;
#pragma unroll
            for (int cc = 0; cc < 32; cc += 2) {
                const float v0 = scr[srow * 68 + cb + cc]     + bias[gcol0 + cc];
                const float v1 = scr[srow * 68 + cb + cc + 1] + bias[gcol0 + cc + 1];
                *(float2*)(orow + cc) = make_float2(v0, v1);
            }
        } else {
            __half* dst;
            if (MODE == 0) {
                dst = g_h16 + (size_t)(z * Sc + grow) * SUBH + gcol0;
            } else {
                dst = g_g16 + (size_t)((z >> 1) * Sc + grow) * (2 * SUBH)
                    + (z & 1) * SUBH + gcol0;
            }
#pragma unroll
            for (int cc = 0; cc < 32; cc += 2) {
                const float g0 = gelu_exact(scr[srow * 68 + cb + cc]     + bias[gcol0 + cc]);
                const float g1 = gelu_exact(scr[srow * 68 + cb + cc + 1] + bias[gcol0 + cc + 1]);
                *(__half2*)(dst + cc) = __float22half2_rn(make_float2(g0, g1));
            }
        }
        __syncwarp();
    }
}

// ============================================================
extern "C" void kernel_launch(void* const* d_in, const int* in_sizes, int n_in,
                              void* d_out, int out_size) {
    const float* x        = (const float*)d_in[0];
    const float* w_switch = (const float*)d_in[1];
    const float* b_switch = (const float*)d_in[2];
    const float* w1       = (const float*)d_in[3];
    const float* b1       = (const float*)d_in[4];
    const float* w2       = (const float*)d_in[5];
    const float* b2       = (const float*)d_in[6];
    const float* w_out    = (const float*)d_in[7];
    const float* b_out    = (const float*)d_in[8];
    float* out = (float*)d_out;

    // 1) routing (proven)
    route_partial_kernel<<<NCHUNKR, 256>>>(x, w_switch);
    route_topk_kernel<<<1, 64>>>(b_switch);

    // 2) weight pre-convert to fp16 (bit-identical to old in-loop conversion)
    {
        __half* w116; cudaGetSymbolAddress((void**)&w116, g_w116);
        __half* w216; cudaGetSymbolAddress((void**)&w216, g_w216);
        __half* wo16; cudaGetSymbolAddress((void**)&wo16, g_wo16);
        const int n1 = Ec * SUBD * SUBH / 4;   // 131072
        const int n2 = Ec * SUBH * SUBH / 4;   // 524288
        const int n3 = 4096 * Dc / 4;          // 1048576
        convert_w_kernel<<<(n1 + 255) / 256, 256>>>((const float4*)w1,    (uint2*)w116, n1);
        convert_w_kernel<<<(n2 + 255) / 256, 256>>>((const float4*)w2,    (uint2*)w216, n2);
        convert_w_kernel<<<(n3 + 255) / 256, 256>>>((const float4*)w_out, (uint2*)wo16, n3);
    }

    // 3) fp16 WMMA expert MLP
    conv_wmma_gemm<0><<<dim3(SUBH / 128, Sc / 128, 16), 256, SMEM_ALLOC>>>(x, b1, nullptr);
    conv_wmma_gemm<1><<<dim3(SUBH / 128, Sc / 128, 16), 256, SMEM_ALLOC>>>(nullptr, b2, nullptr);
    conv_wmma_gemm<2><<<dim3(Dc / 128, Sc / 128, Bc), 256, SMEM_ALLOC>>>(nullptr, b_out, out);
}

// round 17
// speedup vs baseline: 1.5251x; 1.0195x over previous
#include <cuda_runtime.h>
#include <cuda_fp16.h>
#include <mma.h>
#include <math.h>
#include <stdint.h>

using namespace nvcuda;

#define Bc 8
#define Sc 2048
#define Dc 1024
#define Ec 8
#define SUBD 128
#define SUBH 512
#define SD (Sc*Dc)
#define NCHUNKR 256
#define CHUNKR (SD/NCHUNKR)

// ---------------- scratch (static device globals) ----------------
__device__ __align__(16) __half g_x16[(long)Bc*Sc*Dc];       // fp16 x
__device__ __align__(16) __half g_h16[16*Sc*SUBH];           // fp16 h1
__device__ __align__(16) __half g_g16[(long)Bc*Sc*2*SUBH];   // fp16 concat g
__device__ __align__(16) __half g_w116[Ec*SUBD*SUBH];        // fp16 w1 [e][k][n]
__device__ __align__(16) __half g_w216[Ec*SUBH*SUBH];        // fp16 w2 [e][k][n]
__device__ __align__(16) __half g_wo16[4096*Dc];             // fp16 w_out [k][n]
__device__ float g_part[NCHUNKR*Bc*Ec];
__device__ int   g_sel[Bc*2];

__device__ __forceinline__ float gelu_exact(float v) {
    return 0.5f * v * (1.0f + erff(v * 0.70710678118654752440f));
}
__device__ __forceinline__ uint32_t pack_h2(float a, float b) {
    __half2 h; h.x = __float2half_rn(a); h.y = __float2half_rn(b);
    return *(uint32_t*)&h;
}

// ============================================================
// Routing (R1 verbatim — proven)
// ============================================================
__global__ void route_partial_kernel(const float* __restrict__ x,
                                     const float* __restrict__ w) {
    const int chunk = blockIdx.x;
    const int tid   = threadIdx.x;

    float acc[Bc][Ec];
#pragma unroll
    for (int b = 0; b < Bc; b++)
#pragma unroll
        for (int e = 0; e < Ec; e++) acc[b][e] = 0.f;

    const long base = (long)chunk * CHUNKR;
    for (int it = 0; it < CHUNKR / 256; it++) {
        const long i = base + it * 256 + tid;
        const float4 w0 = *(const float4*)(w + i * 8);
        const float4 w1v = *(const float4*)(w + i * 8 + 4);
        const float wv[8] = {w0.x, w0.y, w0.z, w0.w, w1v.x, w1v.y, w1v.z, w1v.w};
#pragma unroll
        for (int b = 0; b < Bc; b++) {
            const float xv = x[(long)b * SD + i];
#pragma unroll
            for (int e = 0; e < Ec; e++) acc[b][e] = fmaf(xv, wv[e], acc[b][e]);
        }
    }

    __shared__ float sm[8][64];
    const int lane = tid & 31, warp = tid >> 5;
#pragma unroll
    for (int b = 0; b < Bc; b++) {
#pragma unroll
        for (int e = 0; e < Ec; e++) {
            float v = acc[b][e];
#pragma unroll
            for (int o = 16; o > 0; o >>= 1) v += __shfl_down_sync(0xffffffffu, v, o);
            if (lane == 0) sm[warp][b * 8 + e] = v;
        }
    }
    __syncthreads();
    if (tid < 64) {
        float s = 0.f;
#pragma unroll
        for (int w2 = 0; w2 < 8; w2++) s += sm[w2][tid];
        g_part[chunk * 64 + tid] = s;
    }
}

__global__ void route_topk_kernel(const float* __restrict__ b_switch) {
    __shared__ float lg[64];
    const int t = threadIdx.x;
    float s = b_switch[t & 7];
    for (int c = 0; c < NCHUNKR; c++) s += g_part[c * 64 + t];
    lg[t] = s;
    __syncthreads();
    if (t < Bc) {
        const float* L = lg + t * 8;
        int i0 = 0; float v0 = L[0];
#pragma unroll
        for (int e = 1; e < 8; e++) if (L[e] > v0) { v0 = L[e]; i0 = e; }
        int i1 = -1; float v1 = -3.0e38f;
#pragma unroll
        for (int e = 0; e < 8; e++) if (e != i0 && L[e] > v1) { v1 = L[e]; i1 = e; }
        g_sel[t * 2 + 0] = i0;
        g_sel[t * 2 + 1] = i1;
    }
}

// ============================================================
// fp32 -> fp16 pre-convert (proven pattern; bit-identical rounding)
// ============================================================
__global__ void convert_f16_kernel(const float4* __restrict__ in,
                                   uint2* __restrict__ out, int n4) {
    const int i = blockIdx.x * blockDim.x + threadIdx.x;
    if (i >= n4) return;
    const float4 v = in[i];
    uint2 h;
    h.x = pack_h2(v.x, v.y);
    h.y = pack_h2(v.z, v.w);
    out[i] = h;
}

// ============================================================
// WMMA fp16 GEMM, uniform 1-term operands, BK=32 double-buffered.
//   A block: 128 rows x [32 halfs|pad8] = 40 halfs/row (80B; 20r%32 distinct)
//   B block: 32 k-rows x [128 halfs|pad8] = 136 halfs/row (272B; 4r%32 distinct)
//   stage = 128*40 + 32*136 = 9472 halfs (18944B); 2 stages = 37888B < 48KB
// MODE 0: g_h16 = gelu(x16[:, e*128:+128] @ w1[e] + b1[e])  K=128 (4 chunks)
// MODE 1: g_g16 = gelu(g_h16 @ w2[e] + b2[e])               K=512 (16 chunks)
// MODE 2: out   = g_g16 @ gather(w_out) + b_out             K=1024 (32 chunks)
// ============================================================
#define AROWE 40
#define ABLK  (128*AROWE)     // 5120 halfs
#define BROWE 136
#define BBLK  (32*BROWE)      // 4352 halfs
#define STAGE_E (ABLK + BBLK) // 9472 halfs
#define SMEM_ALLOC (2*STAGE_E*2)  // 37888 bytes

template <int MODE>
__global__ void __launch_bounds__(256)
wmma_gemm16(const float* __restrict__ bias0, float* __restrict__ outp) {
    extern __shared__ __half smem[];

    const int tid = threadIdx.x;
    const int z = blockIdx.z;
    const int rowBlock = blockIdx.y * 128;
    const int colBlock = blockIdx.x * 128;
    const int warp = tid >> 5, lane = tid & 31;
    const int wm = warp & 3, wn = warp >> 2;

    const __half* A16;
    const __half* Bp16;
    const float* bias;
    int lda, ldn, akbase = 0, nstages, e0 = 0, e1 = 0;
    if (MODE == 0) {
        const int e = g_sel[z];
        A16 = g_x16 + (size_t)(z >> 1) * SD; lda = Dc; akbase = e * SUBD;
        Bp16 = g_w116 + (size_t)e * SUBD * SUBH; ldn = SUBH;
        bias = bias0 + e * SUBH;
        nstages = SUBD / 32;
    } else if (MODE == 1) {
        const int e = g_sel[z];
        A16 = g_h16 + (size_t)z * Sc * SUBH; lda = SUBH;
        Bp16 = g_w216 + (size_t)e * SUBH * SUBH; ldn = SUBH;
        bias = bias0 + e * SUBH;
        nstages = SUBH / 32;
    } else {
        A16 = g_g16 + (size_t)z * Sc * (2 * SUBH); lda = 2 * SUBH;
        Bp16 = g_wo16; ldn = Dc;
        bias = bias0;
        nstages = (2 * SUBH) / 32;
        e0 = g_sel[z * 2]; e1 = g_sel[z * 2 + 1];
    }

    wmma::fragment<wmma::accumulator, 16, 16, 16, float> acc[2][4];
#pragma unroll
    for (int mt = 0; mt < 2; mt++)
#pragma unroll
        for (int nt = 0; nt < 4; nt++) wmma::fill_fragment(acc[mt][nt], 0.0f);

    uint4 pah[2], pbh[2];

    // A: 512 segs (128 rows x 4 segs of 8 halfs); B: 512 segs (32 rows x 16 segs)
    const int mA = tid >> 1, segA = tid & 1;        // j adds +2 segs
    const int kB = tid >> 4, segB = tid & 15;       // j adds +16 rows

    auto loadRegs = [&](int c) {
#pragma unroll
        for (int j = 0; j < 2; j++) {
            pah[j] = *(const uint4*)(A16 + (size_t)(rowBlock + mA) * lda
                                     + akbase + c * 32 + (segA + j * 2) * 8);
            const int kg = c * 32 + kB + j * 16;
            const __half* brow;
            if (MODE == 2) {
                const int r = (kg < SUBH) ? (e0 * SUBH + kg) : (e1 * SUBH + kg - SUBH);
                brow = Bp16 + (size_t)r * Dc;
            } else {
                brow = Bp16 + (size_t)kg * ldn;
            }
            pbh[j] = *(const uint4*)(brow + colBlock + segB * 8);
        }
    };

    auto convStore = [&](int st) {
        __half* s = smem + st * STAGE_E;
#pragma unroll
        for (int j = 0; j < 2; j++) {
            *(uint4*)(s + mA * AROWE + (segA + j * 2) * 8) = pah[j];
            *(uint4*)(s + ABLK + (kB + j * 16) * BROWE + segB * 8) = pbh[j];
        }
    };

    // prologue
    loadRegs(0);
    convStore(0);
    __syncthreads();

    for (int c = 0; c < nstages; c++) {
        if (c + 1 < nstages) loadRegs(c + 1);

        const __half* s = smem + (c & 1) * STAGE_E;
#pragma unroll
        for (int kk = 0; kk < 2; kk++) {
            wmma::fragment<wmma::matrix_a, 16, 16, 16, __half, wmma::row_major> af[2];
#pragma unroll
            for (int mt = 0; mt < 2; mt++)
                wmma::load_matrix_sync(af[mt],
                    s + (wm * 32 + mt * 16) * AROWE + kk * 16, AROWE);
#pragma unroll
            for (int nt = 0; nt < 4; nt++) {
                wmma::fragment<wmma::matrix_b, 16, 16, 16, __half, wmma::row_major> bf;
                wmma::load_matrix_sync(bf,
                    s + ABLK + (kk * 16) * BROWE + wn * 64 + nt * 16, BROWE);
#pragma unroll
                for (int mt = 0; mt < 2; mt++)
                    wmma::mma_sync(acc[mt][nt], af[mt], bf, acc[mt][nt]);
            }
        }

        if (c + 1 < nstages) convStore((c + 1) & 1);
        __syncthreads();
    }

    // ---- epilogue (proven) ----
    float* scr = (float*)smem + warp * (16 * 68);
    const int srow = lane >> 1;
    const int cb = (lane & 1) * 32;

#pragma unroll
    for (int mt = 0; mt < 2; mt++) {
#pragma unroll
        for (int nt = 0; nt < 4; nt++)
            wmma::store_matrix_sync(scr + nt * 16, acc[mt][nt], 68, wmma::mem_row_major);
        __syncwarp();

        const int grow = rowBlock + wm * 32 + mt * 16 + srow;
        const int gcol0 = colBlock + wn * 64 + cb;

        if (MODE == 2) {
            float* orow = outp + (size_t)(z * Sc + grow) * Dc + gcol0;
#pragma unroll
            for (int cc = 0; cc < 32; cc += 2) {
                const float v0 = scr[srow * 68 + cb + cc]     + bias[gcol0 + cc];
                const float v1 = scr[srow * 68 + cb + cc + 1] + bias[gcol0 + cc + 1];
                *(float2*)(orow + cc) = make_float2(v0, v1);
            }
        } else {
            __half* dst;
            if (MODE == 0) {
                dst = g_h16 + (size_t)(z * Sc + grow) * SUBH + gcol0;
            } else {
                dst = g_g16 + (size_t)((z >> 1) * Sc + grow) * (2 * SUBH)
                    + (z & 1) * SUBH + gcol0;
            }
#pragma unroll
            for (int cc = 0; cc < 32; cc += 2) {
                const float g0 = gelu_exact(scr[srow * 68 + cb + cc]     + bias[gcol0 + cc]);
                const float g1 = gelu_exact(scr[srow * 68 + cb + cc + 1] + bias[gcol0 + cc + 1]);
                *(__half2*)(dst + cc) = __float22half2_rn(make_float2(g0, g1));
            }
        }
        __syncwarp();
    }
}

// ============================================================
extern "C" void kernel_launch(void* const* d_in, const int* in_sizes, int n_in,
                              void* d_out, int out_size) {
    const float* x        = (const float*)d_in[0];
    const float* w_switch = (const float*)d_in[1];
    const float* b_switch = (const float*)d_in[2];
    const float* w1       = (const float*)d_in[3];
    const float* b1       = (const float*)d_in[4];
    const float* w2       = (const float*)d_in[5];
    const float* b2       = (const float*)d_in[6];
    const float* w_out    = (const float*)d_in[7];
    const float* b_out    = (const float*)d_in[8];
    float* out = (float*)d_out;

    // 1) routing (proven)
    route_partial_kernel<<<NCHUNKR, 256>>>(x, w_switch);
    route_topk_kernel<<<1, 64>>>(b_switch);

    // 2) pre-convert x and weights to fp16
    {
        __half *x16, *w116, *w216, *wo16;
        cudaGetSymbolAddress((void**)&x16,  g_x16);
        cudaGetSymbolAddress((void**)&w116, g_w116);
        cudaGetSymbolAddress((void**)&w216, g_w216);
        cudaGetSymbolAddress((void**)&wo16, g_wo16);
        const int nx = Bc * Sc * Dc / 4;       // 4194304
        const int n1 = Ec * SUBD * SUBH / 4;   // 131072
        const int n2 = Ec * SUBH * SUBH / 4;   // 524288
        const int n3 = 4096 * Dc / 4;          // 1048576
        convert_f16_kernel<<<(nx + 255) / 256, 256>>>((const float4*)x,     (uint2*)x16,  nx);
        convert_f16_kernel<<<(n1 + 255) / 256, 256>>>((const float4*)w1,    (uint2*)w116, n1);
        convert_f16_kernel<<<(n2 + 255) / 256, 256>>>((const float4*)w2,    (uint2*)w216, n2);
        convert_f16_kernel<<<(n3 + 255) / 256, 256>>>((const float4*)w_out, (uint2*)wo16, n3);
    }

    // 3) fp16 WMMA expert MLP, BK=32
    wmma_gemm16<0><<<dim3(SUBH / 128, Sc / 128, 16), 256, SMEM_ALLOC>>>(b1, nullptr);
    wmma_gemm16<1><<<dim3(SUBH / 128, Sc / 128, 16), 256, SMEM_ALLOC>>>(b2, nullptr);
    wmma_gemm16<2><<<dim3(Dc / 128, Sc / 128, Bc), 256, SMEM_ALLOC>>>(b_out, out);
}